// round 13
// baseline (speedup 1.0000x reference)
#include <cuda_runtime.h>
#include <cuda_fp16.h>
#include <cuda_bf16.h>
#include <math.h>

#define B_  2
#define N_  2048
#define DM_ 128
#define H_  8
#define DK_ 16
#define R_  4
#define GRID_ 64
#define NCELL (GRID_*GRID_)   // 4096
#define NP1 (N_+1)            // 2049

#define PAD_A 136   // halves
#define PAD_W 72

// ---------------- scratch ----------------
__device__ float  g_Q[B_*N_*DM_];
__device__ __align__(16) __half g_Kh[B_*NP1*DM_];
__device__ __align__(16) __half g_Vh[B_*NP1*DM_];
__device__ __align__(16) __half g_att_h[B_*N_*DM_];
__device__ __align__(16) __half g_Wt[4][DM_*DM_];   // [mat][n][k] fp16
__device__ int    g_cellinfo[B_*NCELL];
__device__ int    g_items[B_*N_];
__device__ int    g_ncnt[B_];

__device__ __forceinline__ void mma16816(float* d,
    unsigned a0, unsigned a1, unsigned a2, unsigned a3,
    unsigned b0, unsigned b1)
{
    asm volatile(
        "mma.sync.aligned.m16n8k16.row.col.f32.f16.f16.f32 "
        "{%0,%1,%2,%3}, {%4,%5,%6,%7}, {%8,%9}, {%0,%1,%2,%3};\n"
        : "+f"(d[0]), "+f"(d[1]), "+f"(d[2]), "+f"(d[3])
        : "r"(a0), "r"(a1), "r"(a2), "r"(a3), "r"(b0), "r"(b1));
}

__device__ __forceinline__ void cpa16(__half* dst_smem, const __half* src) {
    unsigned d = (unsigned)__cvta_generic_to_shared(dst_smem);
    asm volatile("cp.async.cg.shared.global [%0], [%1], 16;\n" :: "r"(d), "l"(src));
}
#define CPA_COMMIT() asm volatile("cp.async.commit_group;\n" ::: "memory")
#define CPA_WAIT(N)  asm volatile("cp.async.wait_group %0;\n" :: "n"(N) : "memory")

// ============================================================================
// prepass_W: W fp32 [k][n] -> g_Wt fp16 [n][k]. grid = 64, block = 256
// ============================================================================
__global__ __launch_bounds__(256) void prepass_W(
    const float* __restrict__ Wq, const float* __restrict__ Wk,
    const float* __restrict__ Wv, const float* __restrict__ Wo)
{
    const float* Ws_[4] = {Wq, Wk, Wv, Wo};
    int base = (blockIdx.x*256 + threadIdx.x)*4;
    int m = base >> 14, rem = base & 16383;
    int k = rem >> 7, n = rem & 127;
    float4 wv = *reinterpret_cast<const float4*>(&Ws_[m][k*DM_ + n]);
    g_Wt[m][(n+0)*DM_ + k] = __float2half(wv.x);
    g_Wt[m][(n+1)*DM_ + k] = __float2half(wv.y);
    g_Wt[m][(n+2)*DM_ + k] = __float2half(wv.z);
    g_Wt[m][(n+3)*DM_ + k] = __float2half(wv.w);
}

// ============================================================================
// qkv_fused. grid = 134, block = 256 (unchanged from R11)
// ============================================================================
__global__ __launch_bounds__(256) void qkv_fused(
    const float* __restrict__ z, const float* __restrict__ alive,
    const int*   __restrict__ pos, const float* __restrict__ pt,
    const float* __restrict__ Wk, const float* __restrict__ Wv,
    const float* __restrict__ bq, const float* __restrict__ bk,
    const float* __restrict__ bv)
{
    __shared__ __align__(16) unsigned char smem_raw[45568];
    int tid = threadIdx.x;
    int bx = blockIdx.x;

    if (bx >= 132) {
        int r0 = (bx - 132)*2048;
#pragma unroll
        for (int u = 0; u < 8; u++) {
            int r = r0 + u*256 + tid;
            if (alive[r] == 0.f) {
                uint4 z4 = make_uint4(0u, 0u, 0u, 0u);
                uint4* o = reinterpret_cast<uint4*>(&g_att_h[r*DM_]);
#pragma unroll
                for (int v = 0; v < 16; v++) o[v] = z4;
            }
        }
        return;
    }
    if (bx >= 130) {
        int isV = bx - 130;
        float* p = reinterpret_cast<float*>(smem_raw);
        p[tid] = pt[tid];
        __syncthreads();
        int bb = tid >> 7, cc = tid & 127;
        const float* W    = isV ? Wv : Wk;
        const float* bias = isV ? bv : bk;
        const float* pr = p + bb*128;
        float acc = bias[cc];
#pragma unroll 8
        for (int k2 = 0; k2 < 128; k2++) acc = fmaf(pr[k2], W[k2*DM_ + cc], acc);
        __half* dst = isV ? g_Vh : g_Kh;
        dst[(bb*NP1 + N_)*DM_ + cc] = __float2half(acc);
        return;
    }
    if (bx >= 128) {
        int b = bx - 128;
        int* cnt  = reinterpret_cast<int*>(smem_raw);
        int* wsum = reinterpret_cast<int*>(smem_raw + 16384);
        for (int i = tid; i < NCELL; i += 256) cnt[i] = 0;
        __syncthreads();
        int mycell[8];
#pragma unroll
        for (int u = 0; u < 8; u++) {
            int n = tid + u*256;
            int qid = b*N_ + n;
            mycell[u] = -1;
            if (alive[qid] != 0.f) {
                int2 p = reinterpret_cast<const int2*>(pos)[qid];
                mycell[u] = p.x*GRID_ + p.y;
                atomicAdd(&cnt[mycell[u]], 1);
            }
        }
        __syncthreads();
        int base = tid*16;
        int c[16], s = 0;
#pragma unroll
        for (int k2 = 0; k2 < 16; k2++) { c[k2] = cnt[base+k2]; s += c[k2]; }
        int lane = tid & 31, wid = tid >> 5;
        int v = s;
#pragma unroll
        for (int off = 1; off < 32; off <<= 1) {
            int t = __shfl_up_sync(0xffffffffu, v, off);
            if (lane >= off) v += t;
        }
        if (lane == 31) wsum[wid] = v;
        __syncthreads();
        if (tid < 8) {
            int w = wsum[tid];
#pragma unroll
            for (int off = 1; off < 8; off <<= 1) {
                int t = __shfl_up_sync(0xffu, w, off);
                if (tid >= off) w += t;
            }
            wsum[tid] = w;
        }
        __syncthreads();
        int run = v - s + (wid > 0 ? wsum[wid-1] : 0);
        int starts[16];
#pragma unroll
        for (int k2 = 0; k2 < 16; k2++) {
            starts[k2] = run;
            g_cellinfo[b*NCELL + base + k2] = (run << 16) | c[k2];
            run += c[k2];
        }
        if (tid == 255) g_ncnt[b] = run;
        __syncthreads();
#pragma unroll
        for (int k2 = 0; k2 < 16; k2++) cnt[base+k2] = starts[k2];
        __syncthreads();
#pragma unroll
        for (int u = 0; u < 8; u++) {
            if (mycell[u] >= 0) {
                int slot = atomicAdd(&cnt[mycell[u]], 1);
                g_items[b*N_ + slot] = tid + u*256;
            }
        }
        return;
    }

    // ---- QKV GEMM tile ----
    __half* As = reinterpret_cast<__half*>(smem_raw);
    __half (*Wb)[128*PAD_W] =
        reinterpret_cast<__half(*)[128*PAD_W]>(smem_raw + 8704);

    int row0 = bx * 32;
    int w = tid >> 5, lane = tid & 31;
    int wr = w >> 2, wc = w & 3;
    int rl = wr*16 + (lane >> 2);
    int q2 = (lane & 3) * 2;
    int nb = lane >> 2;

#pragma unroll
    for (int it = 0; it < 4; it++) {
        int i = tid + it*256;
        int n = i >> 3, c8 = (i & 7) * 8;
        cpa16(&Wb[0][n*PAD_W + c8], &g_Wt[0][n*DM_ + c8]);
    }
    CPA_COMMIT();
#pragma unroll
    for (int it = 0; it < 4; it++) {
        int i = tid + it*256;
        int n = i >> 3, c8 = (i & 7) * 8;
        cpa16(&Wb[1][n*PAD_W + c8], &g_Wt[0][n*DM_ + 64 + c8]);
    }
    CPA_COMMIT();

#pragma unroll
    for (int it = 0; it < 2; it++) {
        int i = tid + it*256;
        int r = i >> 4, c8 = (i & 15) * 8;
        float av = alive[row0 + r];
        float4 a = *reinterpret_cast<const float4*>(&z[(row0 + r)*DM_ + c8]);
        float4 b = *reinterpret_cast<const float4*>(&z[(row0 + r)*DM_ + c8 + 4]);
        __half2 h0 = __floats2half2_rn(a.x*av, a.y*av);
        __half2 h1 = __floats2half2_rn(a.z*av, a.w*av);
        __half2 h2 = __floats2half2_rn(b.x*av, b.y*av);
        __half2 h3 = __floats2half2_rn(b.z*av, b.w*av);
        uint4 pk;
        pk.x = *reinterpret_cast<unsigned*>(&h0);
        pk.y = *reinterpret_cast<unsigned*>(&h1);
        pk.z = *reinterpret_cast<unsigned*>(&h2);
        pk.w = *reinterpret_cast<unsigned*>(&h3);
        *reinterpret_cast<uint4*>(&As[r*PAD_A + c8]) = pk;
    }

    const float* biases[3] = {bq, bk, bv};
    float acc[4][4];

#pragma unroll
    for (int c = 0; c < 6; c++) {
        int mat = c >> 1;
        int khalf = c & 1;
        if (khalf == 0) {
#pragma unroll
            for (int nt = 0; nt < 4; nt++) {
                int cc = wc*32 + nt*8 + q2;
                float2 bb = *reinterpret_cast<const float2*>(&biases[mat][cc]);
                acc[nt][0] = bb.x; acc[nt][1] = bb.y;
                acc[nt][2] = bb.x; acc[nt][3] = bb.y;
            }
        }
        if (c == 5) { CPA_WAIT(0); } else { CPA_WAIT(1); }
        __syncthreads();
        const __half* buf = Wb[c & 1];
#pragma unroll
        for (int kt = 0; kt < 4; kt++) {
            int ka = khalf*64 + kt*16 + q2;
            unsigned a0 = *reinterpret_cast<const unsigned*>(&As[rl*PAD_A + ka]);
            unsigned a1 = *reinterpret_cast<const unsigned*>(&As[(rl+8)*PAD_A + ka]);
            unsigned a2 = *reinterpret_cast<const unsigned*>(&As[rl*PAD_A + ka + 8]);
            unsigned a3 = *reinterpret_cast<const unsigned*>(&As[(rl+8)*PAD_A + ka + 8]);
            int kb = kt*16 + q2;
#pragma unroll
            for (int nt = 0; nt < 4; nt++) {
                int n = wc*32 + nt*8 + nb;
                unsigned b0 = *reinterpret_cast<const unsigned*>(&buf[n*PAD_W + kb]);
                unsigned b1 = *reinterpret_cast<const unsigned*>(&buf[n*PAD_W + kb + 8]);
                mma16816(acc[nt], a0, a1, a2, a3, b0, b1);
            }
        }
        if (khalf == 1) {
#pragma unroll
            for (int nt = 0; nt < 4; nt++) {
                int cc = wc*32 + nt*8 + q2;
                int r0g = row0 + rl;
                int r1g = r0g + 8;
                if (mat == 0) {
                    *reinterpret_cast<float2*>(&g_Q[r0g*DM_ + cc]) = make_float2(acc[nt][0], acc[nt][1]);
                    *reinterpret_cast<float2*>(&g_Q[r1g*DM_ + cc]) = make_float2(acc[nt][2], acc[nt][3]);
                } else {
                    __half* dst = (mat == 1) ? g_Kh : g_Vh;
                    int b0i = r0g >> 11, n0i = r0g & (N_-1);
                    int b1i = r1g >> 11, n1i = r1g & (N_-1);
                    *reinterpret_cast<__half2*>(&dst[(b0i*NP1 + n0i)*DM_ + cc]) =
                        __floats2half2_rn(acc[nt][0], acc[nt][1]);
                    *reinterpret_cast<__half2*>(&dst[(b1i*NP1 + n1i)*DM_ + cc]) =
                        __floats2half2_rn(acc[nt][2], acc[nt][3]);
                }
            }
        }
        __syncthreads();
        if (c + 2 < 6) {
            int nc = c + 2;
            const __half* src = &g_Wt[nc >> 1][(nc & 1) * 64];
#pragma unroll
            for (int it = 0; it < 4; it++) {
                int i = tid + it*256;
                int n = i >> 3, c8 = (i & 7) * 8;
                cpa16(&Wb[c & 1][n*PAD_W + c8], &src[n*DM_ + c8]);
            }
            CPA_COMMIT();
        }
    }
}

// ============================================================================
// Sparse attention: warp per ALIVE query; flush loop software-pipelined
// ============================================================================
__global__ __launch_bounds__(256) void attn_kernel(
    const int* __restrict__ pos, const float* __restrict__ rel_bias)
{
    __shared__ float sbias[H_*83];
    __shared__ int   sitem[8][152];
    int tid = threadIdx.x;
    for (int i = tid; i < H_*83; i += 256) {
        int hh = i / 83, idx = i - hh*83;
        sbias[i] = (idx < 81) ? rel_bias[hh*81 + idx] : (idx == 81 ? 0.f : -60.f);
    }
    __syncthreads();

    int warp = tid >> 5, lane = tid & 31;
    int wi = blockIdx.x * 8 + warp;
    int b = wi >> 11, wil = wi & (N_-1);
    if (wil >= g_ncnt[b]) return;
    int n = g_items[b*N_ + wil];
    int qid = b*N_ + n;

    int h = lane >> 2, s = lane & 3;
    int hoff = h * DK_;
    const float* myb = sbias + h*83;
    int* sitem_w = sitem[warp];

    float q[16];
    {
        const float4* qp = reinterpret_cast<const float4*>(g_Q + qid*DM_ + hoff);
#pragma unroll
        for (int u = 0; u < 4; u++) {
            float4 f = qp[u];
            q[4*u+0] = f.x; q[4*u+1] = f.y; q[4*u+2] = f.z; q[4*u+3] = f.w;
        }
    }
    int2 pxy = reinterpret_cast<const int2*>(pos)[qid];
    int xi = pxy.x, yi = pxy.y;

    const __half* kbase = g_Kh + (size_t)b*NP1*DM_;
    const __half* vbase = g_Vh + (size_t)b*NP1*DM_;
    const int* items = g_items + b*N_;
    unsigned lmlt = (1u << lane) - 1u;

    float l = 0.f, acc[16];
#pragma unroll
    for (int u = 0; u < 16; u++) acc[u] = 0.f;

    // software-pipelined flush: prefetch round r+1's K/V while computing r
    auto flushfn = [&](int T4) {
        if (T4 <= 0) return;
        int ent = sitem_w[s];
        uint4 k0, k1, v0, v1;
        {
            int j = ent & 0xffff;
            const uint4* kp = reinterpret_cast<const uint4*>(kbase + (size_t)j*DM_ + hoff);
            k0 = kp[0]; k1 = kp[1];
            const uint4* vp = reinterpret_cast<const uint4*>(vbase + (size_t)j*DM_ + hoff);
            v0 = vp[0]; v1 = vp[1];
        }
        for (int r4 = 0; r4 < T4; r4 += 4) {
            int entn = 0;
            uint4 nk0, nk1, nv0, nv1;
            bool more = (r4 + 4) < T4;
            if (more) {
                entn = sitem_w[r4 + 4 + s];
                int jn = entn & 0xffff;
                const uint4* kp = reinterpret_cast<const uint4*>(kbase + (size_t)jn*DM_ + hoff);
                nk0 = kp[0]; nk1 = kp[1];
                const uint4* vp = reinterpret_cast<const uint4*>(vbase + (size_t)jn*DM_ + hoff);
                nv0 = vp[0]; nv1 = vp[1];
            }
            float rb = myb[ent >> 16];
            float d = 0.f;
            {
                const __half2* h2 = reinterpret_cast<const __half2*>(&k0);
#pragma unroll
                for (int u = 0; u < 4; u++) {
                    float2 f = __half22float2(h2[u]);
                    d = fmaf(q[2*u], f.x, d);
                    d = fmaf(q[2*u+1], f.y, d);
                }
                const __half2* h2b = reinterpret_cast<const __half2*>(&k1);
#pragma unroll
                for (int u = 0; u < 4; u++) {
                    float2 f = __half22float2(h2b[u]);
                    d = fmaf(q[8+2*u], f.x, d);
                    d = fmaf(q[8+2*u+1], f.y, d);
                }
            }
            float p = __expf(fmaf(d, 0.25f, rb));
            l += p;
            {
                const __half2* h2 = reinterpret_cast<const __half2*>(&v0);
#pragma unroll
                for (int u = 0; u < 4; u++) {
                    float2 f = __half22float2(h2[u]);
                    acc[2*u]   = fmaf(p, f.x, acc[2*u]);
                    acc[2*u+1] = fmaf(p, f.y, acc[2*u+1]);
                }
                const __half2* h2b = reinterpret_cast<const __half2*>(&v1);
#pragma unroll
                for (int u = 0; u < 4; u++) {
                    float2 f = __half22float2(h2b[u]);
                    acc[8+2*u]   = fmaf(p, f.x, acc[8+2*u]);
                    acc[8+2*u+1] = fmaf(p, f.y, acc[8+2*u+1]);
                }
            }
            if (more) {
                ent = entn; k0 = nk0; k1 = nk1; v0 = nv0; v1 = nv1;
            }
        }
    };

    int x0 = max(xi - R_, 0), x1 = min(xi + R_, GRID_-1);
    int y0 = max(yi - R_, 0), y1 = min(yi + R_, GRID_-1);
    int T = 0;
    for (int cx = x0; cx <= x1; cx++) {
        int c0 = b*NCELL + (cx << 6);
        int i0 = g_cellinfo[c0 + y0];
        int i1 = g_cellinfo[c0 + y1];
        int st = i0 >> 16;
        int en = (i1 >> 16) + (i1 & 0xffff);
        int bxr = (cx - xi + R_)*9 - yi + R_;
        for (int base = st; base < en; base += 32) {
            int e = base + lane;
            bool valid = false; int j = 0;
            if (e < en) { j = items[e]; valid = (j != n); }
            unsigned mv = __ballot_sync(0xffffffffu, valid);
            if (valid) {
                int yj = pos[(b*N_ + j)*2 + 1];
                sitem_w[T + __popc(mv & lmlt)] = ((bxr + yj) << 16) | j;
            }
            T += __popc(mv);
            if (T >= 112) {
                __syncwarp();
                int T4 = T & ~3;
                flushfn(T4);
                __syncwarp();
                int rem = T - T4;
                int tmp = 0;
                if (lane < rem) tmp = sitem_w[T4 + lane];
                __syncwarp();
                if (lane < rem) sitem_w[lane] = tmp;
                __syncwarp();
                T = rem;
            }
        }
    }
    if (lane == 0) sitem_w[T] = (81 << 16) | N_;
    T++;
    int Tp = (T + 3) & ~3;
    if (lane < Tp - T) sitem_w[T + lane] = (82 << 16) | N_;
    __syncwarp();
    flushfn(Tp);

    unsigned full = 0xffffffffu;
    l += __shfl_xor_sync(full, l, 1);
    l += __shfl_xor_sync(full, l, 2);
#pragma unroll
    for (int u = 0; u < 16; u++) {
        acc[u] += __shfl_xor_sync(full, acc[u], 1);
        acc[u] += __shfl_xor_sync(full, acc[u], 2);
    }
    if (s == 0) {
        float inv = 1.f / l;
        unsigned hw[8];
#pragma unroll
        for (int u = 0; u < 8; u++) {
            __half2 hv = __floats2half2_rn(acc[2*u]*inv, acc[2*u+1]*inv);
            hw[u] = *reinterpret_cast<unsigned*>(&hv);
        }
        uint4* o4 = reinterpret_cast<uint4*>(g_att_h + qid*DM_ + hoff);
        o4[0] = make_uint4(hw[0], hw[1], hw[2], hw[3]);
        o4[1] = make_uint4(hw[4], hw[5], hw[6], hw[7]);
    }
}

// ============================================================================
// Output HMMA GEMM: grid=128 (32-row x 128-col tiles), one cp.async group
// ============================================================================
__global__ __launch_bounds__(256) void out_gemm(
    const float* __restrict__ alive, const float* __restrict__ bo,
    float* __restrict__ out)
{
    __shared__ __align__(16) __half As[32*PAD_A];    // 8704 B
    __shared__ __align__(16) __half Ws[128*PAD_A];   // 34816 B

    int tid = threadIdx.x;
    int row0 = blockIdx.x * 32;
    int w = tid >> 5, lane = tid & 31;
    int wr = w >> 2, wc = w & 3;
    int rl = wr*16 + (lane >> 2);
    int q2 = (lane & 3) * 2;
    int nb = lane >> 2;

    // A: 512 cp (2/thread)
#pragma unroll
    for (int it = 0; it < 2; it++) {
        int i = tid + it*256;
        int r = i >> 4, c8 = (i & 15) * 8;
        cpa16(&As[r*PAD_A + c8], &g_att_h[(row0 + r)*DM_ + c8]);
    }
    // W: 2048 cp (8/thread)
#pragma unroll
    for (int it = 0; it < 8; it++) {
        int i = tid + it*256;
        int n = i >> 4, c8 = (i & 15) * 8;
        cpa16(&Ws[n*PAD_A + c8], &g_Wt[3][n*DM_ + c8]);
    }
    CPA_COMMIT();

    float acc[4][4];
#pragma unroll
    for (int nt = 0; nt < 4; nt++) {
        int c = wc*32 + nt*8 + q2;
        float2 bb = *reinterpret_cast<const float2*>(&bo[c]);
        acc[nt][0] = bb.x; acc[nt][1] = bb.y;
        acc[nt][2] = bb.x; acc[nt][3] = bb.y;
    }

    CPA_WAIT(0);
    __syncthreads();

#pragma unroll
    for (int kt = 0; kt < 8; kt++) {
        int ka = kt*16 + q2;
        unsigned a0 = *reinterpret_cast<const unsigned*>(&As[rl*PAD_A + ka]);
        unsigned a1 = *reinterpret_cast<const unsigned*>(&As[(rl+8)*PAD_A + ka]);
        unsigned a2 = *reinterpret_cast<const unsigned*>(&As[rl*PAD_A + ka + 8]);
        unsigned a3 = *reinterpret_cast<const unsigned*>(&As[(rl+8)*PAD_A + ka + 8]);
#pragma unroll
        for (int nt = 0; nt < 4; nt++) {
            int nB = wc*32 + nt*8 + nb;
            unsigned b0 = *reinterpret_cast<const unsigned*>(&Ws[nB*PAD_A + ka]);
            unsigned b1 = *reinterpret_cast<const unsigned*>(&Ws[nB*PAD_A + ka + 8]);
            mma16816(acc[nt], a0, a1, a2, a3, b0, b1);
        }
    }

#pragma unroll
    for (int nt = 0; nt < 4; nt++) {
        int c = wc*32 + nt*8 + q2;
        int r0g = row0 + rl;
        int r1g = r0g + 8;
        float av0 = alive[r0g], av1 = alive[r1g];
        *reinterpret_cast<float2*>(&out[r0g*DM_ + c]) =
            make_float2(acc[nt][0]*av0, acc[nt][1]*av0);
        *reinterpret_cast<float2*>(&out[r1g*DM_ + c]) =
            make_float2(acc[nt][2]*av1, acc[nt][3]*av1);
    }
}

// ---------------- launch ----------------
extern "C" void kernel_launch(void* const* d_in, const int* in_sizes, int n_in,
                              void* d_out, int out_size)
{
    const float* z     = (const float*)d_in[0];
    const float* pt    = (const float*)d_in[1];
    const int*   pos   = (const int*)  d_in[2];
    const float* alive = (const float*)d_in[3];
    const float* Wq    = (const float*)d_in[4];
    const float* bq    = (const float*)d_in[5];
    const float* Wk    = (const float*)d_in[6];
    const float* bk    = (const float*)d_in[7];
    const float* Wv    = (const float*)d_in[8];
    const float* bv    = (const float*)d_in[9];
    const float* Wo    = (const float*)d_in[10];
    const float* bo    = (const float*)d_in[11];
    const float* rel   = (const float*)d_in[12];
    float* out = (float*)d_out;

    prepass_W<<<64, 256>>>(Wq, Wk, Wv, Wo);
    qkv_fused<<<134, 256>>>(z, alive, pos, pt, Wk, Wv, bq, bk, bv);
    attn_kernel<<<512, 256>>>(pos, rel);
    out_gemm<<<128, 256>>>(alive, bo, out);
}

// round 14
// speedup vs baseline: 1.1759x; 1.1759x over previous
#include <cuda_runtime.h>
#include <cuda_fp16.h>
#include <cuda_bf16.h>
#include <math.h>

#define B_  2
#define N_  2048
#define DM_ 128
#define H_  8
#define DK_ 16
#define R_  4
#define GRID_ 64
#define NCELL (GRID_*GRID_)   // 4096
#define NP1 (N_+1)            // 2049

#define PAD_A 136   // halves
#define PAD_W 72

// ---------------- scratch ----------------
__device__ float  g_Q[B_*N_*DM_];
__device__ __align__(16) __half g_Kh[B_*NP1*DM_];
__device__ __align__(16) __half g_Vh[B_*NP1*DM_];
__device__ __align__(16) __half g_att_h[B_*N_*DM_];
__device__ __align__(16) __half g_Wt[4][DM_*DM_];   // [mat][n][k] fp16
__device__ int    g_cellinfo[B_*NCELL];
__device__ int    g_items[B_*N_];
__device__ int    g_ncnt[B_];

__device__ __forceinline__ void mma16816(float* d,
    unsigned a0, unsigned a1, unsigned a2, unsigned a3,
    unsigned b0, unsigned b1)
{
    asm volatile(
        "mma.sync.aligned.m16n8k16.row.col.f32.f16.f16.f32 "
        "{%0,%1,%2,%3}, {%4,%5,%6,%7}, {%8,%9}, {%0,%1,%2,%3};\n"
        : "+f"(d[0]), "+f"(d[1]), "+f"(d[2]), "+f"(d[3])
        : "r"(a0), "r"(a1), "r"(a2), "r"(a3), "r"(b0), "r"(b1));
}

__device__ __forceinline__ void cpa16(__half* dst_smem, const __half* src) {
    unsigned d = (unsigned)__cvta_generic_to_shared(dst_smem);
    asm volatile("cp.async.cg.shared.global [%0], [%1], 16;\n" :: "r"(d), "l"(src));
}
#define CPA_COMMIT() asm volatile("cp.async.commit_group;\n" ::: "memory")
#define CPA_WAIT(N)  asm volatile("cp.async.wait_group %0;\n" :: "n"(N) : "memory")

// ============================================================================
// prepass_W: Wq/Wk/Wv fp32 [k][n] -> g_Wt fp16 [n][k]. grid = 48, block = 256
// ============================================================================
__global__ __launch_bounds__(256) void prepass_W(
    const float* __restrict__ Wq, const float* __restrict__ Wk,
    const float* __restrict__ Wv)
{
    const float* Ws_[3] = {Wq, Wk, Wv};
    int base = (blockIdx.x*256 + threadIdx.x)*4;
    int m = base >> 14, rem = base & 16383;
    int k = rem >> 7, n = rem & 127;
    float4 wv = *reinterpret_cast<const float4*>(&Ws_[m][k*DM_ + n]);
    g_Wt[m][(n+0)*DM_ + k] = __float2half(wv.x);
    g_Wt[m][(n+1)*DM_ + k] = __float2half(wv.y);
    g_Wt[m][(n+2)*DM_ + k] = __float2half(wv.z);
    g_Wt[m][(n+3)*DM_ + k] = __float2half(wv.w);
}

// ============================================================================
// qkv_fused. grid = 134, block = 256 (R11/R12 version)
// ============================================================================
__global__ __launch_bounds__(256) void qkv_fused(
    const float* __restrict__ z, const float* __restrict__ alive,
    const int*   __restrict__ pos, const float* __restrict__ pt,
    const float* __restrict__ Wk, const float* __restrict__ Wv,
    const float* __restrict__ bq, const float* __restrict__ bk,
    const float* __restrict__ bv)
{
    __shared__ __align__(16) unsigned char smem_raw[45568];
    int tid = threadIdx.x;
    int bx = blockIdx.x;

    if (bx >= 132) {
        int r0 = (bx - 132)*2048;
#pragma unroll
        for (int u = 0; u < 8; u++) {
            int r = r0 + u*256 + tid;
            if (alive[r] == 0.f) {
                uint4 z4 = make_uint4(0u, 0u, 0u, 0u);
                uint4* o = reinterpret_cast<uint4*>(&g_att_h[r*DM_]);
#pragma unroll
                for (int v = 0; v < 16; v++) o[v] = z4;
            }
        }
        return;
    }
    if (bx >= 130) {
        int isV = bx - 130;
        float* p = reinterpret_cast<float*>(smem_raw);
        p[tid] = pt[tid];
        __syncthreads();
        int bb = tid >> 7, cc = tid & 127;
        const float* W    = isV ? Wv : Wk;
        const float* bias = isV ? bv : bk;
        const float* pr = p + bb*128;
        float acc = bias[cc];
#pragma unroll 8
        for (int k2 = 0; k2 < 128; k2++) acc = fmaf(pr[k2], W[k2*DM_ + cc], acc);
        __half* dst = isV ? g_Vh : g_Kh;
        dst[(bb*NP1 + N_)*DM_ + cc] = __float2half(acc);
        return;
    }
    if (bx >= 128) {
        int b = bx - 128;
        int* cnt  = reinterpret_cast<int*>(smem_raw);
        int* wsum = reinterpret_cast<int*>(smem_raw + 16384);
        for (int i = tid; i < NCELL; i += 256) cnt[i] = 0;
        __syncthreads();
        int mycell[8];
#pragma unroll
        for (int u = 0; u < 8; u++) {
            int n = tid + u*256;
            int qid = b*N_ + n;
            mycell[u] = -1;
            if (alive[qid] != 0.f) {
                int2 p = reinterpret_cast<const int2*>(pos)[qid];
                mycell[u] = p.x*GRID_ + p.y;
                atomicAdd(&cnt[mycell[u]], 1);
            }
        }
        __syncthreads();
        int base = tid*16;
        int c[16], s = 0;
#pragma unroll
        for (int k2 = 0; k2 < 16; k2++) { c[k2] = cnt[base+k2]; s += c[k2]; }
        int lane = tid & 31, wid = tid >> 5;
        int v = s;
#pragma unroll
        for (int off = 1; off < 32; off <<= 1) {
            int t = __shfl_up_sync(0xffffffffu, v, off);
            if (lane >= off) v += t;
        }
        if (lane == 31) wsum[wid] = v;
        __syncthreads();
        if (tid < 8) {
            int w = wsum[tid];
#pragma unroll
            for (int off = 1; off < 8; off <<= 1) {
                int t = __shfl_up_sync(0xffu, w, off);
                if (tid >= off) w += t;
            }
            wsum[tid] = w;
        }
        __syncthreads();
        int run = v - s + (wid > 0 ? wsum[wid-1] : 0);
        int starts[16];
#pragma unroll
        for (int k2 = 0; k2 < 16; k2++) {
            starts[k2] = run;
            g_cellinfo[b*NCELL + base + k2] = (run << 16) | c[k2];
            run += c[k2];
        }
        if (tid == 255) g_ncnt[b] = run;
        __syncthreads();
#pragma unroll
        for (int k2 = 0; k2 < 16; k2++) cnt[base+k2] = starts[k2];
        __syncthreads();
#pragma unroll
        for (int u = 0; u < 8; u++) {
            if (mycell[u] >= 0) {
                int slot = atomicAdd(&cnt[mycell[u]], 1);
                g_items[b*N_ + slot] = tid + u*256;
            }
        }
        return;
    }

    // ---- QKV GEMM tile ----
    __half* As = reinterpret_cast<__half*>(smem_raw);
    __half (*Wb)[128*PAD_W] =
        reinterpret_cast<__half(*)[128*PAD_W]>(smem_raw + 8704);

    int row0 = bx * 32;
    int w = tid >> 5, lane = tid & 31;
    int wr = w >> 2, wc = w & 3;
    int rl = wr*16 + (lane >> 2);
    int q2 = (lane & 3) * 2;
    int nb = lane >> 2;

#pragma unroll
    for (int it = 0; it < 4; it++) {
        int i = tid + it*256;
        int n = i >> 3, c8 = (i & 7) * 8;
        cpa16(&Wb[0][n*PAD_W + c8], &g_Wt[0][n*DM_ + c8]);
    }
    CPA_COMMIT();
#pragma unroll
    for (int it = 0; it < 4; it++) {
        int i = tid + it*256;
        int n = i >> 3, c8 = (i & 7) * 8;
        cpa16(&Wb[1][n*PAD_W + c8], &g_Wt[0][n*DM_ + 64 + c8]);
    }
    CPA_COMMIT();

#pragma unroll
    for (int it = 0; it < 2; it++) {
        int i = tid + it*256;
        int r = i >> 4, c8 = (i & 15) * 8;
        float av = alive[row0 + r];
        float4 a = *reinterpret_cast<const float4*>(&z[(row0 + r)*DM_ + c8]);
        float4 b = *reinterpret_cast<const float4*>(&z[(row0 + r)*DM_ + c8 + 4]);
        __half2 h0 = __floats2half2_rn(a.x*av, a.y*av);
        __half2 h1 = __floats2half2_rn(a.z*av, a.w*av);
        __half2 h2 = __floats2half2_rn(b.x*av, b.y*av);
        __half2 h3 = __floats2half2_rn(b.z*av, b.w*av);
        uint4 pk;
        pk.x = *reinterpret_cast<unsigned*>(&h0);
        pk.y = *reinterpret_cast<unsigned*>(&h1);
        pk.z = *reinterpret_cast<unsigned*>(&h2);
        pk.w = *reinterpret_cast<unsigned*>(&h3);
        *reinterpret_cast<uint4*>(&As[r*PAD_A + c8]) = pk;
    }

    const float* biases[3] = {bq, bk, bv};
    float acc[4][4];

#pragma unroll
    for (int c = 0; c < 6; c++) {
        int mat = c >> 1;
        int khalf = c & 1;
        if (khalf == 0) {
#pragma unroll
            for (int nt = 0; nt < 4; nt++) {
                int cc = wc*32 + nt*8 + q2;
                float2 bb = *reinterpret_cast<const float2*>(&biases[mat][cc]);
                acc[nt][0] = bb.x; acc[nt][1] = bb.y;
                acc[nt][2] = bb.x; acc[nt][3] = bb.y;
            }
        }
        if (c == 5) { CPA_WAIT(0); } else { CPA_WAIT(1); }
        __syncthreads();
        const __half* buf = Wb[c & 1];
#pragma unroll
        for (int kt = 0; kt < 4; kt++) {
            int ka = khalf*64 + kt*16 + q2;
            unsigned a0 = *reinterpret_cast<const unsigned*>(&As[rl*PAD_A + ka]);
            unsigned a1 = *reinterpret_cast<const unsigned*>(&As[(rl+8)*PAD_A + ka]);
            unsigned a2 = *reinterpret_cast<const unsigned*>(&As[rl*PAD_A + ka + 8]);
            unsigned a3 = *reinterpret_cast<const unsigned*>(&As[(rl+8)*PAD_A + ka + 8]);
            int kb = kt*16 + q2;
#pragma unroll
            for (int nt = 0; nt < 4; nt++) {
                int n = wc*32 + nt*8 + nb;
                unsigned b0 = *reinterpret_cast<const unsigned*>(&buf[n*PAD_W + kb]);
                unsigned b1 = *reinterpret_cast<const unsigned*>(&buf[n*PAD_W + kb + 8]);
                mma16816(acc[nt], a0, a1, a2, a3, b0, b1);
            }
        }
        if (khalf == 1) {
#pragma unroll
            for (int nt = 0; nt < 4; nt++) {
                int cc = wc*32 + nt*8 + q2;
                int r0g = row0 + rl;
                int r1g = r0g + 8;
                if (mat == 0) {
                    *reinterpret_cast<float2*>(&g_Q[r0g*DM_ + cc]) = make_float2(acc[nt][0], acc[nt][1]);
                    *reinterpret_cast<float2*>(&g_Q[r1g*DM_ + cc]) = make_float2(acc[nt][2], acc[nt][3]);
                } else {
                    __half* dst = (mat == 1) ? g_Kh : g_Vh;
                    int b0i = r0g >> 11, n0i = r0g & (N_-1);
                    int b1i = r1g >> 11, n1i = r1g & (N_-1);
                    *reinterpret_cast<__half2*>(&dst[(b0i*NP1 + n0i)*DM_ + cc]) =
                        __floats2half2_rn(acc[nt][0], acc[nt][1]);
                    *reinterpret_cast<__half2*>(&dst[(b1i*NP1 + n1i)*DM_ + cc]) =
                        __floats2half2_rn(acc[nt][2], acc[nt][3]);
                }
            }
        }
        __syncthreads();
        if (c + 2 < 6) {
            int nc = c + 2;
            const __half* src = &g_Wt[nc >> 1][(nc & 1) * 64];
#pragma unroll
            for (int it = 0; it < 4; it++) {
                int i = tid + it*256;
                int n = i >> 3, c8 = (i & 7) * 8;
                cpa16(&Wb[c & 1][n*PAD_W + c8], &src[n*DM_ + c8]);
            }
            CPA_COMMIT();
        }
    }
}

// ============================================================================
// Sparse attention (R12 flushfn). grid = 528:
//   bx < 512: attention (warp per alive query)
//   bx 512..527: Wo fp32 -> g_Wt[3] fp16 transpose (ready before out_gemm)
// ============================================================================
__global__ __launch_bounds__(256) void attn_kernel(
    const int* __restrict__ pos, const float* __restrict__ rel_bias,
    const float* __restrict__ Wo)
{
    if (blockIdx.x >= 512) {
        int base = ((blockIdx.x - 512)*256 + threadIdx.x)*4;
        int k = base >> 7, n = base & 127;
        float4 wv = *reinterpret_cast<const float4*>(&Wo[k*DM_ + n]);
        g_Wt[3][(n+0)*DM_ + k] = __float2half(wv.x);
        g_Wt[3][(n+1)*DM_ + k] = __float2half(wv.y);
        g_Wt[3][(n+2)*DM_ + k] = __float2half(wv.z);
        g_Wt[3][(n+3)*DM_ + k] = __float2half(wv.w);
        return;
    }

    __shared__ float sbias[H_*83];
    __shared__ int   sitem[8][152];
    int tid = threadIdx.x;
    for (int i = tid; i < H_*83; i += 256) {
        int hh = i / 83, idx = i - hh*83;
        sbias[i] = (idx < 81) ? rel_bias[hh*81 + idx] : (idx == 81 ? 0.f : -60.f);
    }
    __syncthreads();

    int warp = tid >> 5, lane = tid & 31;
    int wi = blockIdx.x * 8 + warp;
    int b = wi >> 11, wil = wi & (N_-1);
    if (wil >= g_ncnt[b]) return;
    int n = g_items[b*N_ + wil];
    int qid = b*N_ + n;

    int h = lane >> 2, s = lane & 3;
    int hoff = h * DK_;
    const float* myb = sbias + h*83;
    int* sitem_w = sitem[warp];

    float q[16];
    {
        const float4* qp = reinterpret_cast<const float4*>(g_Q + qid*DM_ + hoff);
#pragma unroll
        for (int u = 0; u < 4; u++) {
            float4 f = qp[u];
            q[4*u+0] = f.x; q[4*u+1] = f.y; q[4*u+2] = f.z; q[4*u+3] = f.w;
        }
    }
    int2 pxy = reinterpret_cast<const int2*>(pos)[qid];
    int xi = pxy.x, yi = pxy.y;

    const __half* kbase = g_Kh + (size_t)b*NP1*DM_;
    const __half* vbase = g_Vh + (size_t)b*NP1*DM_;
    const int* items = g_items + b*N_;
    unsigned lmlt = (1u << lane) - 1u;

    float l = 0.f, acc[16];
#pragma unroll
    for (int u = 0; u < 16; u++) acc[u] = 0.f;

    auto flushfn = [&](int T4) {
        for (int r4 = 0; r4 < T4; r4 += 4) {
            int ent = sitem_w[r4 + s];
            int j = ent & 0xffff;
            float rb = myb[ent >> 16];
            const uint4* kp = reinterpret_cast<const uint4*>(kbase + (size_t)j*DM_ + hoff);
            uint4 k0 = kp[0], k1 = kp[1];
            const uint4* vp = reinterpret_cast<const uint4*>(vbase + (size_t)j*DM_ + hoff);
            uint4 v0 = vp[0], v1 = vp[1];
            float d = 0.f;
            {
                const __half2* h2 = reinterpret_cast<const __half2*>(&k0);
#pragma unroll
                for (int u = 0; u < 4; u++) {
                    float2 f = __half22float2(h2[u]);
                    d = fmaf(q[2*u], f.x, d);
                    d = fmaf(q[2*u+1], f.y, d);
                }
                const __half2* h2b = reinterpret_cast<const __half2*>(&k1);
#pragma unroll
                for (int u = 0; u < 4; u++) {
                    float2 f = __half22float2(h2b[u]);
                    d = fmaf(q[8+2*u], f.x, d);
                    d = fmaf(q[8+2*u+1], f.y, d);
                }
            }
            float p = __expf(fmaf(d, 0.25f, rb));
            l += p;
            {
                const __half2* h2 = reinterpret_cast<const __half2*>(&v0);
#pragma unroll
                for (int u = 0; u < 4; u++) {
                    float2 f = __half22float2(h2[u]);
                    acc[2*u]   = fmaf(p, f.x, acc[2*u]);
                    acc[2*u+1] = fmaf(p, f.y, acc[2*u+1]);
                }
                const __half2* h2b = reinterpret_cast<const __half2*>(&v1);
#pragma unroll
                for (int u = 0; u < 4; u++) {
                    float2 f = __half22float2(h2b[u]);
                    acc[8+2*u]   = fmaf(p, f.x, acc[8+2*u]);
                    acc[8+2*u+1] = fmaf(p, f.y, acc[8+2*u+1]);
                }
            }
        }
    };

    int x0 = max(xi - R_, 0), x1 = min(xi + R_, GRID_-1);
    int y0 = max(yi - R_, 0), y1 = min(yi + R_, GRID_-1);
    int T = 0;
    for (int cx = x0; cx <= x1; cx++) {
        int c0 = b*NCELL + (cx << 6);
        int i0 = g_cellinfo[c0 + y0];
        int i1 = g_cellinfo[c0 + y1];
        int st = i0 >> 16;
        int en = (i1 >> 16) + (i1 & 0xffff);
        int bxr = (cx - xi + R_)*9 - yi + R_;
        for (int base = st; base < en; base += 32) {
            int e = base + lane;
            bool valid = false; int j = 0;
            if (e < en) { j = items[e]; valid = (j != n); }
            unsigned mv = __ballot_sync(0xffffffffu, valid);
            if (valid) {
                int yj = pos[(b*N_ + j)*2 + 1];
                sitem_w[T + __popc(mv & lmlt)] = ((bxr + yj) << 16) | j;
            }
            T += __popc(mv);
            if (T >= 112) {
                __syncwarp();
                int T4 = T & ~3;
                flushfn(T4);
                __syncwarp();
                int rem = T - T4;
                int tmp = 0;
                if (lane < rem) tmp = sitem_w[T4 + lane];
                __syncwarp();
                if (lane < rem) sitem_w[lane] = tmp;
                __syncwarp();
                T = rem;
            }
        }
    }
    if (lane == 0) sitem_w[T] = (81 << 16) | N_;
    T++;
    int Tp = (T + 3) & ~3;
    if (lane < Tp - T) sitem_w[T + lane] = (82 << 16) | N_;
    __syncwarp();
    flushfn(Tp);

    unsigned full = 0xffffffffu;
    l += __shfl_xor_sync(full, l, 1);
    l += __shfl_xor_sync(full, l, 2);
#pragma unroll
    for (int u = 0; u < 16; u++) {
        acc[u] += __shfl_xor_sync(full, acc[u], 1);
        acc[u] += __shfl_xor_sync(full, acc[u], 2);
    }
    if (s == 0) {
        float inv = 1.f / l;
        unsigned hw[8];
#pragma unroll
        for (int u = 0; u < 8; u++) {
            __half2 hv = __floats2half2_rn(acc[2*u]*inv, acc[2*u+1]*inv);
            hw[u] = *reinterpret_cast<unsigned*>(&hv);
        }
        uint4* o4 = reinterpret_cast<uint4*>(g_att_h + qid*DM_ + hoff);
        o4[0] = make_uint4(hw[0], hw[1], hw[2], hw[3]);
        o4[1] = make_uint4(hw[4], hw[5], hw[6], hw[7]);
    }
}

// ============================================================================
// Output HMMA GEMM: grid=128 (32-row x 128-col tiles), one cp.async group
// ============================================================================
__global__ __launch_bounds__(256) void out_gemm(
    const float* __restrict__ alive, const float* __restrict__ bo,
    float* __restrict__ out)
{
    __shared__ __align__(16) __half As[32*PAD_A];    // 8704 B
    __shared__ __align__(16) __half Ws[128*PAD_A];   // 34816 B

    int tid = threadIdx.x;
    int row0 = blockIdx.x * 32;
    int w = tid >> 5, lane = tid & 31;
    int wr = w >> 2, wc = w & 3;
    int rl = wr*16 + (lane >> 2);
    int q2 = (lane & 3) * 2;
    int nb = lane >> 2;

#pragma unroll
    for (int it = 0; it < 2; it++) {
        int i = tid + it*256;
        int r = i >> 4, c8 = (i & 15) * 8;
        cpa16(&As[r*PAD_A + c8], &g_att_h[(row0 + r)*DM_ + c8]);
    }
#pragma unroll
    for (int it = 0; it < 8; it++) {
        int i = tid + it*256;
        int n = i >> 4, c8 = (i & 15) * 8;
        cpa16(&Ws[n*PAD_A + c8], &g_Wt[3][n*DM_ + c8]);
    }
    CPA_COMMIT();

    float acc[4][4];
#pragma unroll
    for (int nt = 0; nt < 4; nt++) {
        int c = wc*32 + nt*8 + q2;
        float2 bb = *reinterpret_cast<const float2*>(&bo[c]);
        acc[nt][0] = bb.x; acc[nt][1] = bb.y;
        acc[nt][2] = bb.x; acc[nt][3] = bb.y;
    }

    CPA_WAIT(0);
    __syncthreads();

#pragma unroll
    for (int kt = 0; kt < 8; kt++) {
        int ka = kt*16 + q2;
        unsigned a0 = *reinterpret_cast<const unsigned*>(&As[rl*PAD_A + ka]);
        unsigned a1 = *reinterpret_cast<const unsigned*>(&As[(rl+8)*PAD_A + ka]);
        unsigned a2 = *reinterpret_cast<const unsigned*>(&As[rl*PAD_A + ka + 8]);
        unsigned a3 = *reinterpret_cast<const unsigned*>(&As[(rl+8)*PAD_A + ka + 8]);
#pragma unroll
        for (int nt = 0; nt < 4; nt++) {
            int nB = wc*32 + nt*8 + nb;
            unsigned b0 = *reinterpret_cast<const unsigned*>(&Ws[nB*PAD_A + ka]);
            unsigned b1 = *reinterpret_cast<const unsigned*>(&Ws[nB*PAD_A + ka + 8]);
            mma16816(acc[nt], a0, a1, a2, a3, b0, b1);
        }
    }

#pragma unroll
    for (int nt = 0; nt < 4; nt++) {
        int c = wc*32 + nt*8 + q2;
        int r0g = row0 + rl;
        int r1g = r0g + 8;
        float av0 = alive[r0g], av1 = alive[r1g];
        *reinterpret_cast<float2*>(&out[r0g*DM_ + c]) =
            make_float2(acc[nt][0]*av0, acc[nt][1]*av0);
        *reinterpret_cast<float2*>(&out[r1g*DM_ + c]) =
            make_float2(acc[nt][2]*av1, acc[nt][3]*av1);
    }
}

// ---------------- launch ----------------
extern "C" void kernel_launch(void* const* d_in, const int* in_sizes, int n_in,
                              void* d_out, int out_size)
{
    const float* z     = (const float*)d_in[0];
    const float* pt    = (const float*)d_in[1];
    const int*   pos   = (const int*)  d_in[2];
    const float* alive = (const float*)d_in[3];
    const float* Wq    = (const float*)d_in[4];
    const float* bq    = (const float*)d_in[5];
    const float* Wk    = (const float*)d_in[6];
    const float* bk    = (const float*)d_in[7];
    const float* Wv    = (const float*)d_in[8];
    const float* bv    = (const float*)d_in[9];
    const float* Wo    = (const float*)d_in[10];
    const float* bo    = (const float*)d_in[11];
    const float* rel   = (const float*)d_in[12];
    float* out = (float*)d_out;

    prepass_W<<<48, 256>>>(Wq, Wk, Wv);
    qkv_fused<<<134, 256>>>(z, alive, pos, pt, Wk, Wv, bq, bk, bv);
    attn_kernel<<<528, 256>>>(pos, rel, Wo);
    out_gemm<<<128, 256>>>(alive, bo, out);
}

// round 15
// speedup vs baseline: 1.2471x; 1.0606x over previous
#include <cuda_runtime.h>
#include <cuda_fp16.h>
#include <cuda_bf16.h>
#include <math.h>

#define B_  2
#define N_  2048
#define DM_ 128
#define H_  8
#define DK_ 16
#define R_  4
#define GRID_ 64
#define NCELL (GRID_*GRID_)   // 4096
#define NP1 (N_+1)            // 2049

#define PAD_A 136   // halves
#define PAD_W 72

// ---------------- scratch ----------------
__device__ float  g_Q[B_*N_*DM_];
__device__ __align__(16) __half g_Kh[B_*NP1*DM_];
__device__ __align__(16) __half g_Vh[B_*NP1*DM_];
__device__ __align__(16) __half g_att_h[B_*N_*DM_];
__device__ __align__(16) __half g_Wt[4][DM_*DM_];   // [mat][n][k] fp16
__device__ int    g_cellinfo[B_*NCELL];
__device__ int    g_items[B_*N_];       // (y<<11) | n   (n<2048, y<64)
__device__ int    g_ncnt[B_];

__device__ __forceinline__ void mma16816(float* d,
    unsigned a0, unsigned a1, unsigned a2, unsigned a3,
    unsigned b0, unsigned b1)
{
    asm volatile(
        "mma.sync.aligned.m16n8k16.row.col.f32.f16.f16.f32 "
        "{%0,%1,%2,%3}, {%4,%5,%6,%7}, {%8,%9}, {%0,%1,%2,%3};\n"
        : "+f"(d[0]), "+f"(d[1]), "+f"(d[2]), "+f"(d[3])
        : "r"(a0), "r"(a1), "r"(a2), "r"(a3), "r"(b0), "r"(b1));
}

__device__ __forceinline__ void cpa16(__half* dst_smem, const __half* src) {
    unsigned d = (unsigned)__cvta_generic_to_shared(dst_smem);
    asm volatile("cp.async.cg.shared.global [%0], [%1], 16;\n" :: "r"(d), "l"(src));
}
#define CPA_COMMIT() asm volatile("cp.async.commit_group;\n" ::: "memory")
#define CPA_WAIT(N)  asm volatile("cp.async.wait_group %0;\n" :: "n"(N) : "memory")

// ============================================================================
// prepass_W: Wq/Wk/Wv fp32 [k][n] -> g_Wt fp16 [n][k]. grid = 48, block = 256
// ============================================================================
__global__ __launch_bounds__(256) void prepass_W(
    const float* __restrict__ Wq, const float* __restrict__ Wk,
    const float* __restrict__ Wv)
{
    const float* Ws_[3] = {Wq, Wk, Wv};
    int base = (blockIdx.x*256 + threadIdx.x)*4;
    int m = base >> 14, rem = base & 16383;
    int k = rem >> 7, n = rem & 127;
    float4 wv = *reinterpret_cast<const float4*>(&Ws_[m][k*DM_ + n]);
    g_Wt[m][(n+0)*DM_ + k] = __float2half(wv.x);
    g_Wt[m][(n+1)*DM_ + k] = __float2half(wv.y);
    g_Wt[m][(n+2)*DM_ + k] = __float2half(wv.z);
    g_Wt[m][(n+3)*DM_ + k] = __float2half(wv.w);
}

// ============================================================================
// qkv_fused. grid = 134, block = 256
// ============================================================================
__global__ __launch_bounds__(256) void qkv_fused(
    const float* __restrict__ z, const float* __restrict__ alive,
    const int*   __restrict__ pos, const float* __restrict__ pt,
    const float* __restrict__ Wk, const float* __restrict__ Wv,
    const float* __restrict__ bq, const float* __restrict__ bk,
    const float* __restrict__ bv)
{
    __shared__ __align__(16) unsigned char smem_raw[45568];
    int tid = threadIdx.x;
    int bx = blockIdx.x;

    if (bx >= 132) {
        int r0 = (bx - 132)*2048;
#pragma unroll
        for (int u = 0; u < 8; u++) {
            int r = r0 + u*256 + tid;
            if (alive[r] == 0.f) {
                uint4 z4 = make_uint4(0u, 0u, 0u, 0u);
                uint4* o = reinterpret_cast<uint4*>(&g_att_h[r*DM_]);
#pragma unroll
                for (int v = 0; v < 16; v++) o[v] = z4;
            }
        }
        return;
    }
    if (bx >= 130) {
        int isV = bx - 130;
        float* p = reinterpret_cast<float*>(smem_raw);
        p[tid] = pt[tid];
        __syncthreads();
        int bb = tid >> 7, cc = tid & 127;
        const float* W    = isV ? Wv : Wk;
        const float* bias = isV ? bv : bk;
        const float* pr = p + bb*128;
        float acc = bias[cc];
#pragma unroll 8
        for (int k2 = 0; k2 < 128; k2++) acc = fmaf(pr[k2], W[k2*DM_ + cc], acc);
        __half* dst = isV ? g_Vh : g_Kh;
        dst[(bb*NP1 + N_)*DM_ + cc] = __float2half(acc);
        return;
    }
    if (bx >= 128) {
        int b = bx - 128;
        int* cnt  = reinterpret_cast<int*>(smem_raw);
        int* wsum = reinterpret_cast<int*>(smem_raw + 16384);
        for (int i = tid; i < NCELL; i += 256) cnt[i] = 0;
        __syncthreads();
        int mycell[8];
#pragma unroll
        for (int u = 0; u < 8; u++) {
            int n = tid + u*256;
            int qid = b*N_ + n;
            mycell[u] = -1;
            if (alive[qid] != 0.f) {
                int2 p = reinterpret_cast<const int2*>(pos)[qid];
                mycell[u] = p.x*GRID_ + p.y;
                atomicAdd(&cnt[mycell[u]], 1);
            }
        }
        __syncthreads();
        int base = tid*16;
        int c[16], s = 0;
#pragma unroll
        for (int k2 = 0; k2 < 16; k2++) { c[k2] = cnt[base+k2]; s += c[k2]; }
        int lane = tid & 31, wid = tid >> 5;
        int v = s;
#pragma unroll
        for (int off = 1; off < 32; off <<= 1) {
            int t = __shfl_up_sync(0xffffffffu, v, off);
            if (lane >= off) v += t;
        }
        if (lane == 31) wsum[wid] = v;
        __syncthreads();
        if (tid < 8) {
            int w = wsum[tid];
#pragma unroll
            for (int off = 1; off < 8; off <<= 1) {
                int t = __shfl_up_sync(0xffu, w, off);
                if (tid >= off) w += t;
            }
            wsum[tid] = w;
        }
        __syncthreads();
        int run = v - s + (wid > 0 ? wsum[wid-1] : 0);
        int starts[16];
#pragma unroll
        for (int k2 = 0; k2 < 16; k2++) {
            starts[k2] = run;
            g_cellinfo[b*NCELL + base + k2] = (run << 16) | c[k2];
            run += c[k2];
        }
        if (tid == 255) g_ncnt[b] = run;
        __syncthreads();
#pragma unroll
        for (int k2 = 0; k2 < 16; k2++) cnt[base+k2] = starts[k2];
        __syncthreads();
#pragma unroll
        for (int u = 0; u < 8; u++) {
            if (mycell[u] >= 0) {
                int slot = atomicAdd(&cnt[mycell[u]], 1);
                // pack (y<<11) | n so attn never re-reads pos for neighbors
                g_items[b*N_ + slot] = ((mycell[u] & 63) << 11) | (tid + u*256);
            }
        }
        return;
    }

    // ---- QKV GEMM tile ----
    __half* As = reinterpret_cast<__half*>(smem_raw);
    __half (*Wb)[128*PAD_W] =
        reinterpret_cast<__half(*)[128*PAD_W]>(smem_raw + 8704);

    int row0 = bx * 32;
    int w = tid >> 5, lane = tid & 31;
    int wr = w >> 2, wc = w & 3;
    int rl = wr*16 + (lane >> 2);
    int q2 = (lane & 3) * 2;
    int nb = lane >> 2;

#pragma unroll
    for (int it = 0; it < 4; it++) {
        int i = tid + it*256;
        int n = i >> 3, c8 = (i & 7) * 8;
        cpa16(&Wb[0][n*PAD_W + c8], &g_Wt[0][n*DM_ + c8]);
    }
    CPA_COMMIT();
#pragma unroll
    for (int it = 0; it < 4; it++) {
        int i = tid + it*256;
        int n = i >> 3, c8 = (i & 7) * 8;
        cpa16(&Wb[1][n*PAD_W + c8], &g_Wt[0][n*DM_ + 64 + c8]);
    }
    CPA_COMMIT();

#pragma unroll
    for (int it = 0; it < 2; it++) {
        int i = tid + it*256;
        int r = i >> 4, c8 = (i & 15) * 8;
        float av = alive[row0 + r];
        float4 a = *reinterpret_cast<const float4*>(&z[(row0 + r)*DM_ + c8]);
        float4 b = *reinterpret_cast<const float4*>(&z[(row0 + r)*DM_ + c8 + 4]);
        __half2 h0 = __floats2half2_rn(a.x*av, a.y*av);
        __half2 h1 = __floats2half2_rn(a.z*av, a.w*av);
        __half2 h2 = __floats2half2_rn(b.x*av, b.y*av);
        __half2 h3 = __floats2half2_rn(b.z*av, b.w*av);
        uint4 pk;
        pk.x = *reinterpret_cast<unsigned*>(&h0);
        pk.y = *reinterpret_cast<unsigned*>(&h1);
        pk.z = *reinterpret_cast<unsigned*>(&h2);
        pk.w = *reinterpret_cast<unsigned*>(&h3);
        *reinterpret_cast<uint4*>(&As[r*PAD_A + c8]) = pk;
    }

    const float* biases[3] = {bq, bk, bv};
    float acc[4][4];

#pragma unroll
    for (int c = 0; c < 6; c++) {
        int mat = c >> 1;
        int khalf = c & 1;
        if (khalf == 0) {
#pragma unroll
            for (int nt = 0; nt < 4; nt++) {
                int cc = wc*32 + nt*8 + q2;
                float2 bb = *reinterpret_cast<const float2*>(&biases[mat][cc]);
                acc[nt][0] = bb.x; acc[nt][1] = bb.y;
                acc[nt][2] = bb.x; acc[nt][3] = bb.y;
            }
        }
        if (c == 5) { CPA_WAIT(0); } else { CPA_WAIT(1); }
        __syncthreads();
        const __half* buf = Wb[c & 1];
#pragma unroll
        for (int kt = 0; kt < 4; kt++) {
            int ka = khalf*64 + kt*16 + q2;
            unsigned a0 = *reinterpret_cast<const unsigned*>(&As[rl*PAD_A + ka]);
            unsigned a1 = *reinterpret_cast<const unsigned*>(&As[(rl+8)*PAD_A + ka]);
            unsigned a2 = *reinterpret_cast<const unsigned*>(&As[rl*PAD_A + ka + 8]);
            unsigned a3 = *reinterpret_cast<const unsigned*>(&As[(rl+8)*PAD_A + ka + 8]);
            int kb = kt*16 + q2;
#pragma unroll
            for (int nt = 0; nt < 4; nt++) {
                int n = wc*32 + nt*8 + nb;
                unsigned b0 = *reinterpret_cast<const unsigned*>(&buf[n*PAD_W + kb]);
                unsigned b1 = *reinterpret_cast<const unsigned*>(&buf[n*PAD_W + kb + 8]);
                mma16816(acc[nt], a0, a1, a2, a3, b0, b1);
            }
        }
        if (khalf == 1) {
#pragma unroll
            for (int nt = 0; nt < 4; nt++) {
                int cc = wc*32 + nt*8 + q2;
                int r0g = row0 + rl;
                int r1g = r0g + 8;
                if (mat == 0) {
                    *reinterpret_cast<float2*>(&g_Q[r0g*DM_ + cc]) = make_float2(acc[nt][0], acc[nt][1]);
                    *reinterpret_cast<float2*>(&g_Q[r1g*DM_ + cc]) = make_float2(acc[nt][2], acc[nt][3]);
                } else {
                    __half* dst = (mat == 1) ? g_Kh : g_Vh;
                    int b0i = r0g >> 11, n0i = r0g & (N_-1);
                    int b1i = r1g >> 11, n1i = r1g & (N_-1);
                    *reinterpret_cast<__half2*>(&dst[(b0i*NP1 + n0i)*DM_ + cc]) =
                        __floats2half2_rn(acc[nt][0], acc[nt][1]);
                    *reinterpret_cast<__half2*>(&dst[(b1i*NP1 + n1i)*DM_ + cc]) =
                        __floats2half2_rn(acc[nt][2], acc[nt][3]);
                }
            }
        }
        __syncthreads();
        if (c + 2 < 6) {
            int nc = c + 2;
            const __half* src = &g_Wt[nc >> 1][(nc & 1) * 64];
#pragma unroll
            for (int it = 0; it < 4; it++) {
                int i = tid + it*256;
                int n = i >> 3, c8 = (i & 7) * 8;
                cpa16(&Wb[c & 1][n*PAD_W + c8], &src[n*DM_ + c8]);
            }
            CPA_COMMIT();
        }
    }
}

// ============================================================================
// Sparse attention. grid = 528:
//   bx < 512: attention (warp per alive query)
//   bx 512..527: Wo fp32 -> g_Wt[3] fp16 transpose
// ============================================================================
__global__ __launch_bounds__(256) void attn_kernel(
    const int* __restrict__ pos, const float* __restrict__ rel_bias,
    const float* __restrict__ Wo)
{
    if (blockIdx.x >= 512) {
        int base = ((blockIdx.x - 512)*256 + threadIdx.x)*4;
        int k = base >> 7, n = base & 127;
        float4 wv = *reinterpret_cast<const float4*>(&Wo[k*DM_ + n]);
        g_Wt[3][(n+0)*DM_ + k] = __float2half(wv.x);
        g_Wt[3][(n+1)*DM_ + k] = __float2half(wv.y);
        g_Wt[3][(n+2)*DM_ + k] = __float2half(wv.z);
        g_Wt[3][(n+3)*DM_ + k] = __float2half(wv.w);
        return;
    }

    __shared__ float sbias[H_*83];
    __shared__ int   sitem[8][152];
    int tid = threadIdx.x;
    for (int i = tid; i < H_*83; i += 256) {
        int hh = i / 83, idx = i - hh*83;
        sbias[i] = (idx < 81) ? rel_bias[hh*81 + idx] : (idx == 81 ? 0.f : -60.f);
    }
    __syncthreads();

    int warp = tid >> 5, lane = tid & 31;
    int wi = blockIdx.x * 8 + warp;
    int b = wi >> 11, wil = wi & (N_-1);
    if (wil >= g_ncnt[b]) return;
    int n = g_items[b*N_ + wil] & 0x7FF;
    int qid = b*N_ + n;

    int h = lane >> 2, s = lane & 3;
    int hoff = h * DK_;
    const float* myb = sbias + h*83;
    int* sitem_w = sitem[warp];

    float q[16];
    {
        const float4* qp = reinterpret_cast<const float4*>(g_Q + qid*DM_ + hoff);
#pragma unroll
        for (int u = 0; u < 4; u++) {
            float4 f = qp[u];
            q[4*u+0] = f.x; q[4*u+1] = f.y; q[4*u+2] = f.z; q[4*u+3] = f.w;
        }
    }
    int2 pxy = reinterpret_cast<const int2*>(pos)[qid];
    int xi = pxy.x, yi = pxy.y;

    const __half* kbase = g_Kh + (size_t)b*NP1*DM_;
    const __half* vbase = g_Vh + (size_t)b*NP1*DM_;
    const int* items = g_items + b*N_;
    unsigned lmlt = (1u << lane) - 1u;

    float l = 0.f, acc[16];
#pragma unroll
    for (int u = 0; u < 16; u++) acc[u] = 0.f;

    auto flushfn = [&](int T4) {
        for (int r4 = 0; r4 < T4; r4 += 4) {
            int ent = sitem_w[r4 + s];
            int j = ent & 0xffff;
            float rb = myb[ent >> 16];
            const uint4* kp = reinterpret_cast<const uint4*>(kbase + (size_t)j*DM_ + hoff);
            uint4 k0 = kp[0], k1 = kp[1];
            const uint4* vp = reinterpret_cast<const uint4*>(vbase + (size_t)j*DM_ + hoff);
            uint4 v0 = vp[0], v1 = vp[1];
            float d = 0.f;
            {
                const __half2* h2 = reinterpret_cast<const __half2*>(&k0);
#pragma unroll
                for (int u = 0; u < 4; u++) {
                    float2 f = __half22float2(h2[u]);
                    d = fmaf(q[2*u], f.x, d);
                    d = fmaf(q[2*u+1], f.y, d);
                }
                const __half2* h2b = reinterpret_cast<const __half2*>(&k1);
#pragma unroll
                for (int u = 0; u < 4; u++) {
                    float2 f = __half22float2(h2b[u]);
                    d = fmaf(q[8+2*u], f.x, d);
                    d = fmaf(q[8+2*u+1], f.y, d);
                }
            }
            float p = __expf(fmaf(d, 0.25f, rb));
            l += p;
            {
                const __half2* h2 = reinterpret_cast<const __half2*>(&v0);
#pragma unroll
                for (int u = 0; u < 4; u++) {
                    float2 f = __half22float2(h2[u]);
                    acc[2*u]   = fmaf(p, f.x, acc[2*u]);
                    acc[2*u+1] = fmaf(p, f.y, acc[2*u+1]);
                }
                const __half2* h2b = reinterpret_cast<const __half2*>(&v1);
#pragma unroll
                for (int u = 0; u < 4; u++) {
                    float2 f = __half22float2(h2b[u]);
                    acc[8+2*u]   = fmaf(p, f.x, acc[8+2*u]);
                    acc[8+2*u+1] = fmaf(p, f.y, acc[8+2*u+1]);
                }
            }
        }
    };

    int x0 = max(xi - R_, 0), x1 = min(xi + R_, GRID_-1);
    int y0 = max(yi - R_, 0), y1 = min(yi + R_, GRID_-1);
    int T = 0;
    for (int cx = x0; cx <= x1; cx++) {
        int c0 = b*NCELL + (cx << 6);
        int i0 = g_cellinfo[c0 + y0];
        int i1 = g_cellinfo[c0 + y1];
        int st = i0 >> 16;
        int en = (i1 >> 16) + (i1 & 0xffff);
        int bxr = (cx - xi + R_)*9 - yi + R_;
        for (int base = st; base < en; base += 32) {
            int e = base + lane;
            bool valid = false; int jp = 0;
            if (e < en) { jp = items[e]; valid = ((jp & 0x7FF) != n); }
            unsigned mv = __ballot_sync(0xffffffffu, valid);
            if (valid) {
                int jn = jp & 0x7FF;
                int yj = jp >> 11;
                sitem_w[T + __popc(mv & lmlt)] = ((bxr + yj) << 16) | jn;
            }
            T += __popc(mv);
            if (T >= 112) {
                __syncwarp();
                int T4 = T & ~3;
                flushfn(T4);
                __syncwarp();
                int rem = T - T4;
                int tmp = 0;
                if (lane < rem) tmp = sitem_w[T4 + lane];
                __syncwarp();
                if (lane < rem) sitem_w[lane] = tmp;
                __syncwarp();
                T = rem;
            }
        }
    }
    if (lane == 0) sitem_w[T] = (81 << 16) | N_;
    T++;
    int Tp = (T + 3) & ~3;
    if (lane < Tp - T) sitem_w[T + lane] = (82 << 16) | N_;
    __syncwarp();
    flushfn(Tp);

    unsigned full = 0xffffffffu;
    l += __shfl_xor_sync(full, l, 1);
    l += __shfl_xor_sync(full, l, 2);
#pragma unroll
    for (int u = 0; u < 16; u++) {
        acc[u] += __shfl_xor_sync(full, acc[u], 1);
        acc[u] += __shfl_xor_sync(full, acc[u], 2);
    }
    if (s == 0) {
        float inv = 1.f / l;
        unsigned hw[8];
#pragma unroll
        for (int u = 0; u < 8; u++) {
            __half2 hv = __floats2half2_rn(acc[2*u]*inv, acc[2*u+1]*inv);
            hw[u] = *reinterpret_cast<unsigned*>(&hv);
        }
        uint4* o4 = reinterpret_cast<uint4*>(g_att_h + qid*DM_ + hoff);
        o4[0] = make_uint4(hw[0], hw[1], hw[2], hw[3]);
        o4[1] = make_uint4(hw[4], hw[5], hw[6], hw[7]);
    }
}

// ============================================================================
// Output HMMA GEMM: grid=256 (32-row x 64-col tiles), one cp.async group
// ============================================================================
__global__ __launch_bounds__(256) void out_gemm(
    const float* __restrict__ alive, const float* __restrict__ bo,
    float* __restrict__ out)
{
    __shared__ __align__(16) __half As[32*PAD_A];    // 8704 B
    __shared__ __align__(16) __half Ws[64*PAD_A];    // 17408 B

    int tid = threadIdx.x;
    int row0 = (blockIdx.x >> 1) * 32;
    int col0 = (blockIdx.x & 1) * 64;
    int w = tid >> 5, lane = tid & 31;
    int wr = w >> 2, wc = w & 3;       // wr in {0,1}: 16 rows; wc in {0..3}: 16 cols
    int rl = wr*16 + (lane >> 2);
    int q2 = (lane & 3) * 2;
    int nb = lane >> 2;

    // A: 512 cp (2/thread)
#pragma unroll
    for (int it = 0; it < 2; it++) {
        int i = tid + it*256;
        int r = i >> 4, c8 = (i & 15) * 8;
        cpa16(&As[r*PAD_A + c8], &g_att_h[(row0 + r)*DM_ + c8]);
    }
    // W: 64 n-rows x 128 k = 1024 cp (4/thread)
#pragma unroll
    for (int it = 0; it < 4; it++) {
        int i = tid + it*256;
        int nl = i >> 4, c8 = (i & 15) * 8;
        cpa16(&Ws[nl*PAD_A + c8], &g_Wt[3][(col0 + nl)*DM_ + c8]);
    }
    CPA_COMMIT();

    float acc[2][4];
#pragma unroll
    for (int nt = 0; nt < 2; nt++) {
        int c = col0 + wc*16 + nt*8 + q2;
        float2 bb = *reinterpret_cast<const float2*>(&bo[c]);
        acc[nt][0] = bb.x; acc[nt][1] = bb.y;
        acc[nt][2] = bb.x; acc[nt][3] = bb.y;
    }

    CPA_WAIT(0);
    __syncthreads();

#pragma unroll
    for (int kt = 0; kt < 8; kt++) {
        int ka = kt*16 + q2;
        unsigned a0 = *reinterpret_cast<const unsigned*>(&As[rl*PAD_A + ka]);
        unsigned a1 = *reinterpret_cast<const unsigned*>(&As[(rl+8)*PAD_A + ka]);
        unsigned a2 = *reinterpret_cast<const unsigned*>(&As[rl*PAD_A + ka + 8]);
        unsigned a3 = *reinterpret_cast<const unsigned*>(&As[(rl+8)*PAD_A + ka + 8]);
#pragma unroll
        for (int nt = 0; nt < 2; nt++) {
            int nl = wc*16 + nt*8 + nb;
            unsigned b0 = *reinterpret_cast<const unsigned*>(&Ws[nl*PAD_A + ka]);
            unsigned b1 = *reinterpret_cast<const unsigned*>(&Ws[nl*PAD_A + ka + 8]);
            mma16816(acc[nt], a0, a1, a2, a3, b0, b1);
        }
    }

#pragma unroll
    for (int nt = 0; nt < 2; nt++) {
        int c = col0 + wc*16 + nt*8 + q2;
        int r0g = row0 + rl;
        int r1g = r0g + 8;
        float av0 = alive[r0g], av1 = alive[r1g];
        *reinterpret_cast<float2*>(&out[r0g*DM_ + c]) =
            make_float2(acc[nt][0]*av0, acc[nt][1]*av0);
        *reinterpret_cast<float2*>(&out[r1g*DM_ + c]) =
            make_float2(acc[nt][2]*av1, acc[nt][3]*av1);
    }
}

// ---------------- launch ----------------
extern "C" void kernel_launch(void* const* d_in, const int* in_sizes, int n_in,
                              void* d_out, int out_size)
{
    const float* z     = (const float*)d_in[0];
    const float* pt    = (const float*)d_in[1];
    const int*   pos   = (const int*)  d_in[2];
    const float* alive = (const float*)d_in[3];
    const float* Wq    = (const float*)d_in[4];
    const float* bq    = (const float*)d_in[5];
    const float* Wk    = (const float*)d_in[6];
    const float* bk    = (const float*)d_in[7];
    const float* Wv    = (const float*)d_in[8];
    const float* bv    = (const float*)d_in[9];
    const float* Wo    = (const float*)d_in[10];
    const float* bo    = (const float*)d_in[11];
    const float* rel   = (const float*)d_in[12];
    float* out = (float*)d_out;

    prepass_W<<<48, 256>>>(Wq, Wk, Wv);
    qkv_fused<<<134, 256>>>(z, alive, pos, pt, Wk, Wv, bq, bk, bv);
    attn_kernel<<<528, 256>>>(pos, rel, Wo);
    out_gemm<<<256, 256>>>(alive, bo, out);
}